// round 3
// baseline (speedup 1.0000x reference)
#include <cuda_runtime.h>
#include <math.h>

#define N 8192
#define D 64
#define THREADS 128
#define ROWS_PER_BLOCK 128
#define JSPLITS 16
#define JRANGE (N / JSPLITS)   // 512
#define TILE_J 128
#define KNN 16

typedef unsigned long long ull;

__device__ float g_norms[N];
__device__ float g_scratch[N * JSPLITS * KNN];  // partial top-16 d^2 per (row, split)
__device__ float g_mean[N];

// packed 2xfp32 FMA (Blackwell FFMA2) — only reachable via PTX
__device__ __forceinline__ ull ffma2(ull a, ull b, ull c) {
    ull d;
    asm("fma.rn.f32x2 %0, %1, %2, %3;" : "=l"(d) : "l"(a), "l"(b), "l"(c));
    return d;
}
__device__ __forceinline__ ull fadd2(ull a, ull b) {
    ull d;
    asm("add.rn.f32x2 %0, %1, %2;" : "=l"(d) : "l"(a), "l"(b));
    return d;
}
__device__ __forceinline__ float lo32(ull v) { return __uint_as_float((unsigned)(v & 0xffffffffu)); }
__device__ __forceinline__ float hi32(ull v) { return __uint_as_float((unsigned)(v >> 32)); }

__global__ void norms_kernel(const float* __restrict__ x) {
    int i = blockIdx.x * blockDim.x + threadIdx.x;
    if (i >= N) return;
    const float4* p = (const float4*)(x + (size_t)i * D);
    float s = 0.f;
#pragma unroll
    for (int q = 0; q < D / 4; q++) {
        float4 v = p[q];
        s += v.x * v.x + v.y * v.y + v.z * v.z + v.w * v.w;
    }
    g_norms[i] = s;
}

__global__ void __launch_bounds__(THREADS, 4) knn_kernel(const float* __restrict__ x) {
    __shared__ float sj[TILE_J][D];   // 32 KB tile of candidate points
    __shared__ float sn[TILE_J];      // their norms

    const int rowBlock = blockIdx.x;          // 0..63
    const int split    = blockIdx.y;          // 0..JSPLITS-1
    const int i        = rowBlock * ROWS_PER_BLOCK + threadIdx.x;

    // query point in registers, packed as 32 x f32x2
    ull xi2[D / 2];
#pragma unroll
    for (int q = 0; q < D / 4; q++) {
        ulonglong2 v = ((const ulonglong2*)(x + (size_t)i * D))[q];
        xi2[2 * q + 0] = v.x;
        xi2[2 * q + 1] = v.y;
    }
    const float x2i = g_norms[i];

    float t[KNN];
#pragma unroll
    for (int q = 0; q < KNN; q++) t[q] = 3.4e38f;
    float thr = 3.4e38f;

    const int j0 = split * JRANGE;

    for (int tile = 0; tile < JRANGE; tile += TILE_J) {
        __syncthreads();
        {
            const float4* src = (const float4*)(x + (size_t)(j0 + tile) * D);
            float4* dst = (float4*)(&sj[0][0]);
            for (int q = threadIdx.x; q < TILE_J * D / 4; q += THREADS) dst[q] = src[q];
            if (threadIdx.x < TILE_J) sn[threadIdx.x] = g_norms[j0 + tile + threadIdx.x];
        }
        __syncthreads();

#pragma unroll 1
        for (int jj = 0; jj < TILE_J; jj++) {
            const ulonglong2* row = (const ulonglong2*)(&sj[jj][0]);  // 16 x 16B
            ull a0 = 0, a1 = 0, a2 = 0, a3 = 0;
#pragma unroll
            for (int q = 0; q < 8; q++) {
                ulonglong2 v0 = row[2 * q + 0];
                ulonglong2 v1 = row[2 * q + 1];
                a0 = ffma2(xi2[4 * q + 0], v0.x, a0);
                a1 = ffma2(xi2[4 * q + 1], v0.y, a1);
                a2 = ffma2(xi2[4 * q + 2], v1.x, a2);
                a3 = ffma2(xi2[4 * q + 3], v1.y, a3);
            }
            ull s01 = fadd2(a0, a1);
            ull s23 = fadd2(a2, a3);
            ull s   = fadd2(s01, s23);
            float dot = lo32(s) + hi32(s);
            float d2 = fmaf(-2.f, dot, x2i + sn[jj]);
            int jg = j0 + tile + jj;
            if (jg != i && d2 < thr) {
                float m = t[0]; int mi = 0;
#pragma unroll
                for (int q = 1; q < KNN; q++) { if (t[q] > m) { m = t[q]; mi = q; } }
#pragma unroll
                for (int q = 0; q < KNN; q++) { if (q == mi) t[q] = d2; }
                float nm = t[0];
#pragma unroll
                for (int q = 1; q < KNN; q++) nm = fmaxf(nm, t[q]);
                thr = nm;
            }
        }
    }

    float* out = g_scratch + ((size_t)i * JSPLITS + split) * KNN;
#pragma unroll
    for (int q = 0; q < KNN; q++) out[q] = t[q];
}

__global__ void merge_kernel() {
    int i = blockIdx.x * blockDim.x + threadIdx.x;
    if (i >= N) return;
    const float* c = g_scratch + (size_t)i * (JSPLITS * KNN);

    float t[KNN];
#pragma unroll
    for (int q = 0; q < KNN; q++) t[q] = 3.4e38f;
    float thr = 3.4e38f;

    for (int j = 0; j < JSPLITS * KNN; j++) {
        float d2 = c[j];
        if (d2 < thr) {
            float m = t[0]; int mi = 0;
#pragma unroll
            for (int q = 1; q < KNN; q++) { if (t[q] > m) { m = t[q]; mi = q; } }
#pragma unroll
            for (int q = 0; q < KNN; q++) { if (q == mi) t[q] = d2; }
            float nm = t[0];
#pragma unroll
            for (int q = 1; q < KNN; q++) nm = fmaxf(nm, t[q]);
            thr = nm;
        }
    }

    float s = 0.f;
#pragma unroll
    for (int q = 0; q < KNN; q++) s += (t[q] > 0.f) ? sqrtf(t[q]) : 0.f;
    g_mean[i] = s * (1.f / (float)KNN);
}

__global__ void loss_kernel(float* __restrict__ out) {
    __shared__ float s1[1024];
    __shared__ float s2[1024];
    int tid = threadIdx.x;

    float mx = -3.4e38f;
    for (int i = tid; i < N; i += 1024) mx = fmaxf(mx, g_mean[i]);
    s1[tid] = mx;
    __syncthreads();
    for (int o = 512; o > 0; o >>= 1) {
        if (tid < o) s1[tid] = fmaxf(s1[tid], s1[tid + o]);
        __syncthreads();
    }
    mx = s1[0];
    __syncthreads();

    float se = 0.f, sm = 0.f;
    for (int i = tid; i < N; i += 1024) {
        float v = g_mean[i];
        se += expf(v - mx);
        sm += v;
    }
    s1[tid] = se;
    s2[tid] = sm;
    __syncthreads();
    for (int o = 512; o > 0; o >>= 1) {
        if (tid < o) { s1[tid] += s1[tid + o]; s2[tid] += s2[tid + o]; }
        __syncthreads();
    }
    if (tid == 0) {
        float lse  = mx + logf(s1[0]);
        float mean = s2[0] / (float)N;
        out[0] = lse - mean - logf((float)N);
    }
}

extern "C" void kernel_launch(void* const* d_in, const int* in_sizes, int n_in,
                              void* d_out, int out_size) {
    const float* x = (const float*)d_in[0];
    (void)in_sizes; (void)n_in; (void)out_size;

    norms_kernel<<<N / 128, 128>>>(x);
    dim3 grid(N / ROWS_PER_BLOCK, JSPLITS);
    knn_kernel<<<grid, THREADS>>>(x);
    merge_kernel<<<N / 128, 128>>>();
    loss_kernel<<<1, 1024>>>((float*)d_out);
}

// round 5
// speedup vs baseline: 2.0474x; 2.0474x over previous
#include <cuda_runtime.h>
#include <cuda_bf16.h>
#include <math.h>

#define N 8192
#define D 64
#define ROWS 128
#define TILE_N 128
#define JSPLITS 2
#define JRANGE (N / JSPLITS)       // 4096
#define NTILES (JRANGE / TILE_N)   // 32
#define K17 17
#define THREADS 256
#define NLISTS 8                   // JSPLITS * 4 column-lanes

// smem layout (dynamic)
#define SM_XN  0
#define SM_BN  512
#define SM_AHI 1024
#define SM_ALO 17408
#define SM_BHI 33792
#define SM_BLO 50176
#define SMEM_TOTAL 66560

__device__ unsigned g_xhi[N * 32];          // bf16 hi pairs
__device__ unsigned g_xlo[N * 32];          // bf16 lo pairs
__device__ float    g_norms[N];
__device__ float    g_part[NLISTS * K17 * N];  // [list][q][i] (coalesced merge)
__device__ float    g_mean[N];

__device__ __forceinline__ unsigned smem_u32(const void* p) {
    unsigned a;
    asm("{ .reg .u64 t; cvta.to.shared.u64 t, %1; cvt.u32.u64 %0, t; }" : "=r"(a) : "l"(p));
    return a;
}

__device__ __forceinline__ void ldsm4(unsigned& r0, unsigned& r1, unsigned& r2, unsigned& r3,
                                      unsigned addr) {
    asm volatile("ldmatrix.sync.aligned.m8n8.x4.shared.b16 {%0,%1,%2,%3}, [%4];"
                 : "=r"(r0), "=r"(r1), "=r"(r2), "=r"(r3) : "r"(addr));
}

__device__ __forceinline__ void mma16816(float& c0, float& c1, float& c2, float& c3,
                                         unsigned a0, unsigned a1, unsigned a2, unsigned a3,
                                         unsigned b0, unsigned b1) {
    asm volatile("mma.sync.aligned.m16n8k16.row.col.f32.bf16.bf16.f32 "
                 "{%0,%1,%2,%3}, {%4,%5,%6,%7}, {%8,%9}, {%0,%1,%2,%3};"
                 : "+f"(c0), "+f"(c1), "+f"(c2), "+f"(c3)
                 : "r"(a0), "r"(a1), "r"(a2), "r"(a3), "r"(b0), "r"(b1));
}

__device__ __forceinline__ void bubble17(float (&t)[K17], float v) {
#pragma unroll
    for (int q = 0; q < K17; q++) {
        float lo = fminf(t[q], v);
        v = fmaxf(t[q], v);
        t[q] = lo;
    }
}

__global__ void prep_kernel(const float* __restrict__ x) {
    int i = blockIdx.x * blockDim.x + threadIdx.x;
    if (i >= N) return;
    const float* xr = x + (size_t)i * D;
    float s = 0.f;
#pragma unroll
    for (int q = 0; q < 32; q++) {
        float f0 = xr[2 * q], f1 = xr[2 * q + 1];
        s += f0 * f0 + f1 * f1;
        __nv_bfloat16 h0 = __float2bfloat16(f0);
        __nv_bfloat16 h1 = __float2bfloat16(f1);
        __nv_bfloat16 g0 = __float2bfloat16(f0 - __bfloat162float(h0));
        __nv_bfloat16 g1 = __float2bfloat16(f1 - __bfloat162float(h1));
        g_xhi[i * 32 + q] = (unsigned)__bfloat16_as_ushort(h0) | ((unsigned)__bfloat16_as_ushort(h1) << 16);
        g_xlo[i * 32 + q] = (unsigned)__bfloat16_as_ushort(g0) | ((unsigned)__bfloat16_as_ushort(g1) << 16);
    }
    g_norms[i] = s;
}

__global__ void __launch_bounds__(THREADS) knn_kernel() {
    extern __shared__ char smem[];
    const unsigned sbase = smem_u32(smem);
    const int tid  = threadIdx.x;
    const int lane = tid & 31;
    const int wid  = tid >> 5;          // 0..7, owns rows wid*16 .. +15
    const int rowblk = blockIdx.x;
    const int split  = blockIdx.y;

    // ---- load A (this CTA's 128 rows), swizzled for ldmatrix ----
    for (int idx = tid; idx < 1024; idx += THREADS) {
        int r = idx >> 3, q = idx & 7;
        int sw = r * 8 + (q ^ (r & 7));
        ((uint4*)(smem + SM_AHI))[sw] = ((const uint4*)g_xhi)[(size_t)(rowblk * ROWS + r) * 8 + q];
        ((uint4*)(smem + SM_ALO))[sw] = ((const uint4*)g_xlo)[(size_t)(rowblk * ROWS + r) * 8 + q];
    }
    if (tid < 128) ((float*)(smem + SM_XN))[tid] = g_norms[rowblk * ROWS + tid];
    __syncthreads();

    const int g  = lane >> 2;   // row within 8-group
    const int t2 = lane & 3;    // column lane
    const float xn0 = ((const float*)(smem + SM_XN))[wid * 16 + g];
    const float xn1 = ((const float*)(smem + SM_XN))[wid * 16 + g + 8];

    float t0[K17], t1[K17];
#pragma unroll
    for (int q = 0; q < K17; q++) { t0[q] = 3.4e38f; t1[q] = 3.4e38f; }
    float thr0 = 3.4e38f, thr1 = 3.4e38f;

    // precomputed ldmatrix address components
    const unsigned a_row = (unsigned)(wid * 16 + (lane & 15));
    const unsigned a_chbase = (unsigned)(lane >> 4);       // + 2k
    const unsigned a_swz = (unsigned)(lane & 7);
    const unsigned b_row = (unsigned)((lane & 7) + ((lane >> 4) & 1) * 8);  // + p*16
    const unsigned b_chbase = (unsigned)((lane >> 3) & 1); // + 2k

    for (int tile = 0; tile < NTILES; tile++) {
        const int j0 = split * JRANGE + tile * TILE_N;
        __syncthreads();   // previous tile's B fully consumed
        for (int idx = tid; idx < 1024; idx += THREADS) {
            int r = idx >> 3, q = idx & 7;
            int sw = r * 8 + (q ^ (r & 7));
            ((uint4*)(smem + SM_BHI))[sw] = ((const uint4*)g_xhi)[(size_t)(j0 + r) * 8 + q];
            ((uint4*)(smem + SM_BLO))[sw] = ((const uint4*)g_xlo)[(size_t)(j0 + r) * 8 + q];
        }
        if (tid < 128) ((float*)(smem + SM_BN))[tid] = g_norms[j0 + tid];
        __syncthreads();

        float acc[16][4];
#pragma unroll
        for (int nt = 0; nt < 16; nt++)
#pragma unroll
            for (int s = 0; s < 4; s++) acc[nt][s] = 0.f;

#pragma unroll
        for (int k = 0; k < 4; k++) {
            unsigned ach = (2u * k + a_chbase) ^ a_swz;
            unsigned aoff = sbase + SM_AHI + a_row * 128 + ach * 16;
            unsigned AH0, AH1, AH2, AH3, AL0, AL1, AL2, AL3;
            ldsm4(AH0, AH1, AH2, AH3, aoff);
            ldsm4(AL0, AL1, AL2, AL3, aoff + (SM_ALO - SM_AHI));
#pragma unroll
            for (int p = 0; p < 8; p++) {
                unsigned br = b_row + p * 16;
                unsigned bch = (2u * k + b_chbase) ^ (br & 7);
                unsigned boff = sbase + SM_BHI + br * 128 + bch * 16;
                unsigned BH0, BH1, BH2, BH3, BL0, BL1, BL2, BL3;
                ldsm4(BH0, BH1, BH2, BH3, boff);
                ldsm4(BL0, BL1, BL2, BL3, boff + (SM_BLO - SM_BHI));
                mma16816(acc[2*p][0], acc[2*p][1], acc[2*p][2], acc[2*p][3],
                         AH0, AH1, AH2, AH3, BH0, BH1);
                mma16816(acc[2*p+1][0], acc[2*p+1][1], acc[2*p+1][2], acc[2*p+1][3],
                         AH0, AH1, AH2, AH3, BH2, BH3);
                mma16816(acc[2*p][0], acc[2*p][1], acc[2*p][2], acc[2*p][3],
                         AH0, AH1, AH2, AH3, BL0, BL1);
                mma16816(acc[2*p+1][0], acc[2*p+1][1], acc[2*p+1][2], acc[2*p+1][3],
                         AH0, AH1, AH2, AH3, BL2, BL3);
                mma16816(acc[2*p][0], acc[2*p][1], acc[2*p][2], acc[2*p][3],
                         AL0, AL1, AL2, AL3, BH0, BH1);
                mma16816(acc[2*p+1][0], acc[2*p+1][1], acc[2*p+1][2], acc[2*p+1][3],
                         AL0, AL1, AL2, AL3, BH2, BH3);
            }
        }

        // ---- epilogue: d^2 + gated top-17 insert ----
        const float* bn = (const float*)(smem + SM_BN);
#pragma unroll
        for (int nt = 0; nt < 16; nt++) {
            int c = nt * 8 + 2 * t2;
            float b0 = bn[c], b1 = bn[c + 1];
            float v0 = fmaf(-2.f, acc[nt][0], xn0 + b0);
            float v1 = fmaf(-2.f, acc[nt][1], xn0 + b1);
            float v2 = fmaf(-2.f, acc[nt][2], xn1 + b0);
            float v3 = fmaf(-2.f, acc[nt][3], xn1 + b1);
            if (v0 <= thr0) { bubble17(t0, v0); thr0 = fminf(thr0, t0[16]); }
            if (v1 <= thr0) { bubble17(t0, v1); thr0 = fminf(thr0, t0[16]); }
            if (v2 <= thr1) { bubble17(t1, v2); thr1 = fminf(thr1, t1[16]); }
            if (v3 <= thr1) { bubble17(t1, v3); thr1 = fminf(thr1, t1[16]); }
        }
        // quad-shared conservative threshold (min of 4 lanes' 17th values)
        {
            float a = t0[16];
            a = fminf(a, __shfl_xor_sync(0xffffffffu, a, 1));
            a = fminf(a, __shfl_xor_sync(0xffffffffu, a, 2));
            thr0 = fminf(thr0, a);
            float b = t1[16];
            b = fminf(b, __shfl_xor_sync(0xffffffffu, b, 1));
            b = fminf(b, __shfl_xor_sync(0xffffffffu, b, 2));
            thr1 = fminf(thr1, b);
        }
    }

    // write partial lists: layout [list][q][i]
    const int i0 = rowblk * ROWS + wid * 16 + g;
    const int li = split * 4 + t2;
#pragma unroll
    for (int q = 0; q < K17; q++) {
        g_part[((size_t)li * K17 + q) * N + i0]     = t0[q];
        g_part[((size_t)li * K17 + q) * N + i0 + 8] = t1[q];
    }
}

__global__ void merge_kernel() {
    int i = blockIdx.x * blockDim.x + threadIdx.x;
    if (i >= N) return;
    float t[K17];
#pragma unroll
    for (int q = 0; q < K17; q++) t[q] = 3.4e38f;
    for (int l = 0; l < NLISTS; l++) {
#pragma unroll
        for (int q = 0; q < K17; q++) {
            float v = g_part[((size_t)l * K17 + q) * N + i];
            if (v < t[16]) bubble17(t, v);
        }
    }
    // t[0] = self (d^2 ~ 0): drop; mean distance over next 16
    float s = 0.f;
#pragma unroll
    for (int q = 1; q < K17; q++) s += (t[q] > 0.f) ? sqrtf(t[q]) : 0.f;
    g_mean[i] = s * (1.f / 16.f);
}

__global__ void loss_kernel(float* __restrict__ out) {
    __shared__ float r1[32];
    __shared__ float r2[32];
    int tid = threadIdx.x, lane = tid & 31, wid = tid >> 5;

    float mx = -3.4e38f;
    for (int i = tid; i < N; i += 1024) mx = fmaxf(mx, g_mean[i]);
#pragma unroll
    for (int o = 16; o > 0; o >>= 1) mx = fmaxf(mx, __shfl_xor_sync(0xffffffffu, mx, o));
    if (lane == 0) r1[wid] = mx;
    __syncthreads();
    mx = r1[0];
#pragma unroll
    for (int q = 1; q < 32; q++) mx = fmaxf(mx, r1[q]);
    __syncthreads();

    float se = 0.f, sm = 0.f;
    for (int i = tid; i < N; i += 1024) {
        float v = g_mean[i];
        se += expf(v - mx);
        sm += v;
    }
#pragma unroll
    for (int o = 16; o > 0; o >>= 1) {
        se += __shfl_xor_sync(0xffffffffu, se, o);
        sm += __shfl_xor_sync(0xffffffffu, sm, o);
    }
    if (lane == 0) { r1[wid] = se; r2[wid] = sm; }
    __syncthreads();
    if (tid == 0) {
        float tse = 0.f, tsm = 0.f;
#pragma unroll
        for (int q = 0; q < 32; q++) { tse += r1[q]; tsm += r2[q]; }
        float lse  = mx + logf(tse);
        float mean = tsm / (float)N;
        out[0] = lse - mean - logf((float)N);
    }
}

extern "C" void kernel_launch(void* const* d_in, const int* in_sizes, int n_in,
                              void* d_out, int out_size) {
    const float* x = (const float*)d_in[0];
    (void)in_sizes; (void)n_in; (void)out_size;
    cudaFuncSetAttribute(knn_kernel, cudaFuncAttributeMaxDynamicSharedMemorySize, SMEM_TOTAL);
    prep_kernel<<<N / 128, 128>>>(x);
    dim3 grid(N / ROWS, JSPLITS);
    knn_kernel<<<grid, THREADS, SMEM_TOTAL>>>();
    merge_kernel<<<N / 128, 128>>>();
    loss_kernel<<<1, 1024>>>((float*)d_out);
}

// round 6
// speedup vs baseline: 2.3005x; 1.1236x over previous
#include <cuda_runtime.h>
#include <cuda_bf16.h>
#include <math.h>

#define N 8192
#define D 64
#define ROWS 128
#define TILE_N 128
#define JSPLITS 2
#define JRANGE (N / JSPLITS)       // 4096
#define NTILES (JRANGE / TILE_N)   // 32
#define K17 17
#define THREADS 256
#define NLISTS 8

// smem layout (dynamic)
#define SM_XN    0
#define SM_BN(b) (512 + (b) * 512)
#define SM_AHI   2048
#define SM_ALO   18432
#define SM_BHI(b) (34816 + (b) * 32768)
#define HILO_DELTA 16384
#define SMEM_TOTAL 100352

__device__ unsigned g_xhi[N * 32];
__device__ unsigned g_xlo[N * 32];
__device__ float    g_norms[N];
__device__ float    g_part[NLISTS * K17 * N];
__device__ float    g_mean[N];

__device__ __forceinline__ unsigned smem_u32(const void* p) {
    unsigned a;
    asm("{ .reg .u64 t; cvta.to.shared.u64 t, %1; cvt.u32.u64 %0, t; }" : "=r"(a) : "l"(p));
    return a;
}
__device__ __forceinline__ void cp16(unsigned dst, const void* src) {
    asm volatile("cp.async.cg.shared.global [%0], [%1], 16;" :: "r"(dst), "l"(src) : "memory");
}
#define CP_COMMIT() asm volatile("cp.async.commit_group;" ::: "memory")
#define CP_WAIT1()  asm volatile("cp.async.wait_group 1;" ::: "memory")
#define CP_WAIT0()  asm volatile("cp.async.wait_group 0;" ::: "memory")

__device__ __forceinline__ void ldsm4(unsigned& r0, unsigned& r1, unsigned& r2, unsigned& r3,
                                      unsigned addr) {
    asm volatile("ldmatrix.sync.aligned.m8n8.x4.shared.b16 {%0,%1,%2,%3}, [%4];"
                 : "=r"(r0), "=r"(r1), "=r"(r2), "=r"(r3) : "r"(addr));
}
__device__ __forceinline__ void mma16816(float& c0, float& c1, float& c2, float& c3,
                                         unsigned a0, unsigned a1, unsigned a2, unsigned a3,
                                         unsigned b0, unsigned b1) {
    asm volatile("mma.sync.aligned.m16n8k16.row.col.f32.bf16.bf16.f32 "
                 "{%0,%1,%2,%3}, {%4,%5,%6,%7}, {%8,%9}, {%0,%1,%2,%3};"
                 : "+f"(c0), "+f"(c1), "+f"(c2), "+f"(c3)
                 : "r"(a0), "r"(a1), "r"(a2), "r"(a3), "r"(b0), "r"(b1));
}
__device__ __forceinline__ void bubble17(float (&t)[K17], float v) {
#pragma unroll
    for (int q = 0; q < K17; q++) {
        float lo = fminf(t[q], v);
        v = fmaxf(t[q], v);
        t[q] = lo;
    }
}

__global__ void prep_kernel(const float* __restrict__ x) {
    int i = blockIdx.x * blockDim.x + threadIdx.x;
    if (i >= N) return;
    const float* xr = x + (size_t)i * D;
    float s = 0.f;
#pragma unroll
    for (int q = 0; q < 32; q++) {
        float f0 = xr[2 * q], f1 = xr[2 * q + 1];
        s += f0 * f0 + f1 * f1;
        __nv_bfloat16 h0 = __float2bfloat16(f0);
        __nv_bfloat16 h1 = __float2bfloat16(f1);
        __nv_bfloat16 g0 = __float2bfloat16(f0 - __bfloat162float(h0));
        __nv_bfloat16 g1 = __float2bfloat16(f1 - __bfloat162float(h1));
        g_xhi[i * 32 + q] = (unsigned)__bfloat16_as_ushort(h0) | ((unsigned)__bfloat16_as_ushort(h1) << 16);
        g_xlo[i * 32 + q] = (unsigned)__bfloat16_as_ushort(g0) | ((unsigned)__bfloat16_as_ushort(g1) << 16);
    }
    g_norms[i] = s;
}

__device__ __forceinline__ void load_b_tile(char* smem, int tid, int j0, int b) {
    // 2048 cp.async of 16B: hi (1024) + lo (1024), swizzled dst
    const unsigned sbase = smem_u32(smem);
#pragma unroll
    for (int it = 0; it < 4; it++) {
        int idx = tid + it * THREADS;          // 0..1023
        int r = idx >> 3, q = idx & 7;
        int sw = r * 8 + (q ^ (r & 7));
        cp16(sbase + SM_BHI(b) + sw * 16, &((const uint4*)g_xhi)[(size_t)(j0 + r) * 8 + q]);
        cp16(sbase + SM_BHI(b) + HILO_DELTA + sw * 16, &((const uint4*)g_xlo)[(size_t)(j0 + r) * 8 + q]);
    }
    if (tid < 32) cp16(sbase + SM_BN(b) + tid * 16, &g_norms[j0 + tid * 4]);
}

__global__ void __launch_bounds__(THREADS) knn_kernel() {
    extern __shared__ char smem[];
    const unsigned sbase = smem_u32(smem);
    const int tid  = threadIdx.x;
    const int lane = tid & 31;
    const int wid  = tid >> 5;
    const int rowblk = blockIdx.x;
    const int split  = blockIdx.y;

    // A tiles (hi/lo), swizzled for ldmatrix
    for (int idx = tid; idx < 1024; idx += THREADS) {
        int r = idx >> 3, q = idx & 7;
        int sw = r * 8 + (q ^ (r & 7));
        ((uint4*)(smem + SM_AHI))[sw] = ((const uint4*)g_xhi)[(size_t)(rowblk * ROWS + r) * 8 + q];
        ((uint4*)(smem + SM_ALO))[sw] = ((const uint4*)g_xlo)[(size_t)(rowblk * ROWS + r) * 8 + q];
    }
    if (tid < 128) ((float*)(smem + SM_XN))[tid] = g_norms[rowblk * ROWS + tid];

    // prologue: prefetch tile 0
    load_b_tile(smem, tid, split * JRANGE, 0);
    CP_COMMIT();

    const int g  = lane >> 2;
    const int t2 = lane & 3;

    float t0[K17], t1[K17];
#pragma unroll
    for (int q = 0; q < K17; q++) { t0[q] = 3.4e38f; t1[q] = 3.4e38f; }
    float thr0 = 3.4e38f, thr1 = 3.4e38f;
    float xn0 = 0.f, xn1 = 0.f;

    const unsigned a_row = (unsigned)(wid * 16 + (lane & 15));
    const unsigned a_chbase = (unsigned)(lane >> 4);
    const unsigned a_swz = (unsigned)(lane & 7);
    const unsigned b_row = (unsigned)((lane & 7) + ((lane >> 4) & 1) * 8);
    const unsigned b_chbase = (unsigned)((lane >> 3) & 1);

    for (int tile = 0; tile < NTILES; tile++) {
        const int b = tile & 1;
        if (tile + 1 < NTILES) {
            load_b_tile(smem, tid, split * JRANGE + (tile + 1) * TILE_N, 1 - b);
            CP_COMMIT();
            CP_WAIT1();
        } else {
            CP_WAIT0();
        }
        __syncthreads();
        if (tile == 0) {
            xn0 = ((const float*)(smem + SM_XN))[wid * 16 + g];
            xn1 = ((const float*)(smem + SM_XN))[wid * 16 + g + 8];
        }

        float acc[16][4];
#pragma unroll
        for (int nt = 0; nt < 16; nt++)
#pragma unroll
            for (int s = 0; s < 4; s++) acc[nt][s] = 0.f;

#pragma unroll
        for (int k = 0; k < 4; k++) {
            unsigned ach = (2u * k + a_chbase) ^ a_swz;
            unsigned aoff = sbase + SM_AHI + a_row * 128 + ach * 16;
            unsigned AH0, AH1, AH2, AH3, AL0, AL1, AL2, AL3;
            ldsm4(AH0, AH1, AH2, AH3, aoff);
            ldsm4(AL0, AL1, AL2, AL3, aoff + (SM_ALO - SM_AHI));
#pragma unroll
            for (int p = 0; p < 8; p++) {
                unsigned br = b_row + p * 16;
                unsigned bch = (2u * k + b_chbase) ^ (br & 7);
                unsigned boff = sbase + SM_BHI(b) + br * 128 + bch * 16;
                unsigned BH0, BH1, BH2, BH3, BL0, BL1, BL2, BL3;
                ldsm4(BH0, BH1, BH2, BH3, boff);
                ldsm4(BL0, BL1, BL2, BL3, boff + HILO_DELTA);
                mma16816(acc[2*p][0], acc[2*p][1], acc[2*p][2], acc[2*p][3],
                         AH0, AH1, AH2, AH3, BH0, BH1);
                mma16816(acc[2*p+1][0], acc[2*p+1][1], acc[2*p+1][2], acc[2*p+1][3],
                         AH0, AH1, AH2, AH3, BH2, BH3);
                mma16816(acc[2*p][0], acc[2*p][1], acc[2*p][2], acc[2*p][3],
                         AH0, AH1, AH2, AH3, BL0, BL1);
                mma16816(acc[2*p+1][0], acc[2*p+1][1], acc[2*p+1][2], acc[2*p+1][3],
                         AH0, AH1, AH2, AH3, BL2, BL3);
                mma16816(acc[2*p][0], acc[2*p][1], acc[2*p][2], acc[2*p][3],
                         AL0, AL1, AL2, AL3, BH0, BH1);
                mma16816(acc[2*p+1][0], acc[2*p+1][1], acc[2*p+1][2], acc[2*p+1][3],
                         AL0, AL1, AL2, AL3, BH2, BH3);
            }
        }

        // epilogue: d^2 + quad-gated top-17 insert
        const float* bn = (const float*)(smem + SM_BN(b));
#pragma unroll
        for (int nt = 0; nt < 16; nt++) {
            int c = nt * 8 + 2 * t2;
            float b0 = bn[c], b1 = bn[c + 1];
            float v0 = fmaf(-2.f, acc[nt][0], xn0 + b0);
            float v1 = fmaf(-2.f, acc[nt][1], xn0 + b1);
            float v2 = fmaf(-2.f, acc[nt][2], xn1 + b0);
            float v3 = fmaf(-2.f, acc[nt][3], xn1 + b1);
            if (v0 < thr0) bubble17(t0, v0);
            if (v1 < thr0) bubble17(t0, v1);
            if (v2 < thr1) bubble17(t1, v2);
            if (v3 < thr1) bubble17(t1, v3);
            // quad-shared threshold refresh (exact for merged top-17)
            float q0 = t0[16];
            q0 = fminf(q0, __shfl_xor_sync(0xffffffffu, q0, 1));
            q0 = fminf(q0, __shfl_xor_sync(0xffffffffu, q0, 2));
            thr0 = q0;
            float q1 = t1[16];
            q1 = fminf(q1, __shfl_xor_sync(0xffffffffu, q1, 1));
            q1 = fminf(q1, __shfl_xor_sync(0xffffffffu, q1, 2));
            thr1 = q1;
        }
        __syncthreads();   // all warps done with buf b before it is overwritten
    }

    const int i0 = rowblk * ROWS + wid * 16 + g;
    const int li = split * 4 + t2;
#pragma unroll
    for (int q = 0; q < K17; q++) {
        g_part[((size_t)li * K17 + q) * N + i0]     = t0[q];
        g_part[((size_t)li * K17 + q) * N + i0 + 8] = t1[q];
    }
}

__global__ void merge_kernel() {
    int i = blockIdx.x * blockDim.x + threadIdx.x;
    if (i >= N) return;
    float t[K17];
#pragma unroll
    for (int q = 0; q < K17; q++) t[q] = 3.4e38f;
    for (int l = 0; l < NLISTS; l++) {
#pragma unroll
        for (int q = 0; q < K17; q++) {
            float v = g_part[((size_t)l * K17 + q) * N + i];
            if (v < t[16]) bubble17(t, v);
        }
    }
    float s = 0.f;
#pragma unroll
    for (int q = 1; q < K17; q++) s += (t[q] > 0.f) ? sqrtf(t[q]) : 0.f;
    g_mean[i] = s * (1.f / 16.f);
}

__global__ void loss_kernel(float* __restrict__ out) {
    __shared__ float r1[32];
    __shared__ float r2[32];
    int tid = threadIdx.x, lane = tid & 31, wid = tid >> 5;

    float mx = -3.4e38f;
    for (int i = tid; i < N; i += 1024) mx = fmaxf(mx, g_mean[i]);
#pragma unroll
    for (int o = 16; o > 0; o >>= 1) mx = fmaxf(mx, __shfl_xor_sync(0xffffffffu, mx, o));
    if (lane == 0) r1[wid] = mx;
    __syncthreads();
    mx = r1[0];
#pragma unroll
    for (int q = 1; q < 32; q++) mx = fmaxf(mx, r1[q]);
    __syncthreads();

    float se = 0.f, sm = 0.f;
    for (int i = tid; i < N; i += 1024) {
        float v = g_mean[i];
        se += expf(v - mx);
        sm += v;
    }
#pragma unroll
    for (int o = 16; o > 0; o >>= 1) {
        se += __shfl_xor_sync(0xffffffffu, se, o);
        sm += __shfl_xor_sync(0xffffffffu, sm, o);
    }
    if (lane == 0) { r1[wid] = se; r2[wid] = sm; }
    __syncthreads();
    if (tid == 0) {
        float tse = 0.f, tsm = 0.f;
#pragma unroll
        for (int q = 0; q < 32; q++) { tse += r1[q]; tsm += r2[q]; }
        float lse  = mx + logf(tse);
        float mean = tsm / (float)N;
        out[0] = lse - mean - logf((float)N);
    }
}

extern "C" void kernel_launch(void* const* d_in, const int* in_sizes, int n_in,
                              void* d_out, int out_size) {
    const float* x = (const float*)d_in[0];
    (void)in_sizes; (void)n_in; (void)out_size;
    cudaFuncSetAttribute(knn_kernel, cudaFuncAttributeMaxDynamicSharedMemorySize, SMEM_TOTAL);
    prep_kernel<<<N / 128, 128>>>(x);
    dim3 grid(N / ROWS, JSPLITS);
    knn_kernel<<<grid, THREADS, SMEM_TOTAL>>>();
    merge_kernel<<<N / 128, 128>>>();
    loss_kernel<<<1, 1024>>>((float*)d_out);
}

// round 7
// speedup vs baseline: 2.7740x; 1.2058x over previous
#include <cuda_runtime.h>
#include <cuda_fp16.h>
#include <math.h>

#define N 8192
#define D 64
#define ROWS 128
#define TILE_N 128
#define JSPLITS 2
#define JRANGE (N / JSPLITS)       // 4096
#define NTILES (JRANGE / TILE_N)   // 32
#define K17 17
#define THREADS 256
#define NLISTS 8

// smem layout (dynamic)
#define SM_XN    0
#define SM_BN(b) (512 + (b) * 512)
#define SM_A     2048
#define SM_B(b)  (18432 + (b) * 16384)
#define SMEM_TOTAL 51200

__device__ unsigned g_xf[N * 32];          // fp16 pairs
__device__ float    g_norms[N];
__device__ float    g_part[NLISTS * K17 * N];
__device__ float    g_mean[N];

__device__ __forceinline__ unsigned smem_u32(const void* p) {
    unsigned a;
    asm("{ .reg .u64 t; cvta.to.shared.u64 t, %1; cvt.u32.u64 %0, t; }" : "=r"(a) : "l"(p));
    return a;
}
__device__ __forceinline__ void cp16(unsigned dst, const void* src) {
    asm volatile("cp.async.cg.shared.global [%0], [%1], 16;" :: "r"(dst), "l"(src) : "memory");
}
#define CP_COMMIT() asm volatile("cp.async.commit_group;" ::: "memory")
#define CP_WAIT1()  asm volatile("cp.async.wait_group 1;" ::: "memory")
#define CP_WAIT0()  asm volatile("cp.async.wait_group 0;" ::: "memory")

__device__ __forceinline__ void ldsm4(unsigned& r0, unsigned& r1, unsigned& r2, unsigned& r3,
                                      unsigned addr) {
    asm volatile("ldmatrix.sync.aligned.m8n8.x4.shared.b16 {%0,%1,%2,%3}, [%4];"
                 : "=r"(r0), "=r"(r1), "=r"(r2), "=r"(r3) : "r"(addr));
}
__device__ __forceinline__ void mma16816(float& c0, float& c1, float& c2, float& c3,
                                         unsigned a0, unsigned a1, unsigned a2, unsigned a3,
                                         unsigned b0, unsigned b1) {
    asm volatile("mma.sync.aligned.m16n8k16.row.col.f32.f16.f16.f32 "
                 "{%0,%1,%2,%3}, {%4,%5,%6,%7}, {%8,%9}, {%0,%1,%2,%3};"
                 : "+f"(c0), "+f"(c1), "+f"(c2), "+f"(c3)
                 : "r"(a0), "r"(a1), "r"(a2), "r"(a3), "r"(b0), "r"(b1));
}
__device__ __forceinline__ void bubble17(float (&t)[K17], float v) {
#pragma unroll
    for (int q = 0; q < K17; q++) {
        float lo = fminf(t[q], v);
        v = fmaxf(t[q], v);
        t[q] = lo;
    }
}

__global__ void prep_kernel(const float* __restrict__ x) {
    int i = blockIdx.x * blockDim.x + threadIdx.x;
    if (i >= N) return;
    const float* xr = x + (size_t)i * D;
    float s = 0.f;
#pragma unroll
    for (int q = 0; q < 32; q++) {
        float f0 = xr[2 * q], f1 = xr[2 * q + 1];
        s += f0 * f0 + f1 * f1;
        __half h0 = __float2half(f0);
        __half h1 = __float2half(f1);
        g_xf[i * 32 + q] = (unsigned)__half_as_ushort(h0) | ((unsigned)__half_as_ushort(h1) << 16);
    }
    g_norms[i] = s;
}

__device__ __forceinline__ void load_b_tile(char* smem, int tid, int j0, int b) {
    const unsigned sbase = smem_u32(smem);
#pragma unroll
    for (int it = 0; it < 4; it++) {
        int idx = tid + it * THREADS;          // 0..1023
        int r = idx >> 3, q = idx & 7;
        int sw = r * 8 + (q ^ (r & 7));
        cp16(sbase + SM_B(b) + sw * 16, &((const uint4*)g_xf)[(size_t)(j0 + r) * 8 + q]);
    }
    if (tid < 32) cp16(sbase + SM_BN(b) + tid * 16, &g_norms[j0 + tid * 4]);
}

__global__ void __launch_bounds__(THREADS) knn_kernel() {
    extern __shared__ char smem[];
    const unsigned sbase = smem_u32(smem);
    const int tid  = threadIdx.x;
    const int lane = tid & 31;
    const int wid  = tid >> 5;
    const int rowblk = blockIdx.x;
    const int split  = blockIdx.y;

    // A tile, swizzled for ldmatrix
    for (int idx = tid; idx < 1024; idx += THREADS) {
        int r = idx >> 3, q = idx & 7;
        int sw = r * 8 + (q ^ (r & 7));
        ((uint4*)(smem + SM_A))[sw] = ((const uint4*)g_xf)[(size_t)(rowblk * ROWS + r) * 8 + q];
    }
    if (tid < 128) ((float*)(smem + SM_XN))[tid] = g_norms[rowblk * ROWS + tid];

    load_b_tile(smem, tid, split * JRANGE, 0);
    CP_COMMIT();

    const int g  = lane >> 2;
    const int t2 = lane & 3;

    float t0[K17], t1[K17];
#pragma unroll
    for (int q = 0; q < K17; q++) { t0[q] = 3.4e38f; t1[q] = 3.4e38f; }
    float thr0 = 3.4e38f, thr1 = 3.4e38f;
    float xn0 = 0.f, xn1 = 0.f;

    const unsigned a_row = (unsigned)(wid * 16 + (lane & 15));
    const unsigned a_chbase = (unsigned)(lane >> 4);
    const unsigned a_swz = (unsigned)(lane & 7);
    const unsigned b_row = (unsigned)((lane & 7) + ((lane >> 4) & 1) * 8);
    const unsigned b_chbase = (unsigned)((lane >> 3) & 1);

    for (int tile = 0; tile < NTILES; tile++) {
        const int b = tile & 1;
        if (tile + 1 < NTILES) {
            load_b_tile(smem, tid, split * JRANGE + (tile + 1) * TILE_N, 1 - b);
            CP_COMMIT();
            CP_WAIT1();
        } else {
            CP_WAIT0();
        }
        __syncthreads();
        if (tile == 0) {
            xn0 = ((const float*)(smem + SM_XN))[wid * 16 + g];
            xn1 = ((const float*)(smem + SM_XN))[wid * 16 + g + 8];
        }

        float acc[16][4];
#pragma unroll
        for (int nt = 0; nt < 16; nt++)
#pragma unroll
            for (int s = 0; s < 4; s++) acc[nt][s] = 0.f;

#pragma unroll
        for (int k = 0; k < 4; k++) {
            unsigned ach = (2u * k + a_chbase) ^ a_swz;
            unsigned aoff = sbase + SM_A + a_row * 128 + ach * 16;
            unsigned A0, A1, A2, A3;
            ldsm4(A0, A1, A2, A3, aoff);
#pragma unroll
            for (int p = 0; p < 8; p++) {
                unsigned br = b_row + p * 16;
                unsigned bch = (2u * k + b_chbase) ^ (br & 7);
                unsigned boff = sbase + SM_B(b) + br * 128 + bch * 16;
                unsigned B0, B1, B2, B3;
                ldsm4(B0, B1, B2, B3, boff);
                mma16816(acc[2*p][0], acc[2*p][1], acc[2*p][2], acc[2*p][3],
                         A0, A1, A2, A3, B0, B1);
                mma16816(acc[2*p+1][0], acc[2*p+1][1], acc[2*p+1][2], acc[2*p+1][3],
                         A0, A1, A2, A3, B2, B3);
            }
        }

        // epilogue: d^2 + quad-gated top-17 insert
        const float* bn = (const float*)(smem + SM_BN(b));
#pragma unroll
        for (int nt = 0; nt < 16; nt++) {
            int c = nt * 8 + 2 * t2;
            float b0 = bn[c], b1 = bn[c + 1];
            float v0 = fmaf(-2.f, acc[nt][0], xn0 + b0);
            float v1 = fmaf(-2.f, acc[nt][1], xn0 + b1);
            float v2 = fmaf(-2.f, acc[nt][2], xn1 + b0);
            float v3 = fmaf(-2.f, acc[nt][3], xn1 + b1);
            if (v0 < thr0) bubble17(t0, v0);
            if (v1 < thr0) bubble17(t0, v1);
            if (v2 < thr1) bubble17(t1, v2);
            if (v3 < thr1) bubble17(t1, v3);
            float q0 = t0[16];
            q0 = fminf(q0, __shfl_xor_sync(0xffffffffu, q0, 1));
            q0 = fminf(q0, __shfl_xor_sync(0xffffffffu, q0, 2));
            thr0 = q0;
            float q1 = t1[16];
            q1 = fminf(q1, __shfl_xor_sync(0xffffffffu, q1, 1));
            q1 = fminf(q1, __shfl_xor_sync(0xffffffffu, q1, 2));
            thr1 = q1;
        }
        __syncthreads();
    }

    const int i0 = rowblk * ROWS + wid * 16 + g;
    const int li = split * 4 + t2;
#pragma unroll
    for (int q = 0; q < K17; q++) {
        g_part[((size_t)li * K17 + q) * N + i0]     = t0[q];
        g_part[((size_t)li * K17 + q) * N + i0 + 8] = t1[q];
    }
}

__global__ void merge_kernel() {
    int i = blockIdx.x * blockDim.x + threadIdx.x;
    if (i >= N) return;
    float t[K17];
#pragma unroll
    for (int q = 0; q < K17; q++) t[q] = 3.4e38f;
    for (int l = 0; l < NLISTS; l++) {
#pragma unroll
        for (int q = 0; q < K17; q++) {
            float v = g_part[((size_t)l * K17 + q) * N + i];
            if (v < t[16]) bubble17(t, v);
        }
    }
    float s = 0.f;
#pragma unroll
    for (int q = 1; q < K17; q++) s += (t[q] > 0.f) ? sqrtf(t[q]) : 0.f;
    g_mean[i] = s * (1.f / 16.f);
}

__global__ void loss_kernel(float* __restrict__ out) {
    __shared__ float r1[32];
    __shared__ float r2[32];
    int tid = threadIdx.x, lane = tid & 31, wid = tid >> 5;

    float mx = -3.4e38f;
    for (int i = tid; i < N; i += 1024) mx = fmaxf(mx, g_mean[i]);
#pragma unroll
    for (int o = 16; o > 0; o >>= 1) mx = fmaxf(mx, __shfl_xor_sync(0xffffffffu, mx, o));
    if (lane == 0) r1[wid] = mx;
    __syncthreads();
    mx = r1[0];
#pragma unroll
    for (int q = 1; q < 32; q++) mx = fmaxf(mx, r1[q]);
    __syncthreads();

    float se = 0.f, sm = 0.f;
    for (int i = tid; i < N; i += 1024) {
        float v = g_mean[i];
        se += expf(v - mx);
        sm += v;
    }
#pragma unroll
    for (int o = 16; o > 0; o >>= 1) {
        se += __shfl_xor_sync(0xffffffffu, se, o);
        sm += __shfl_xor_sync(0xffffffffu, sm, o);
    }
    if (lane == 0) { r1[wid] = se; r2[wid] = sm; }
    __syncthreads();
    if (tid == 0) {
        float tse = 0.f, tsm = 0.f;
#pragma unroll
        for (int q = 0; q < 32; q++) { tse += r1[q]; tsm += r2[q]; }
        float lse  = mx + logf(tse);
        float mean = tsm / (float)N;
        out[0] = lse - mean - logf((float)N);
    }
}

extern "C" void kernel_launch(void* const* d_in, const int* in_sizes, int n_in,
                              void* d_out, int out_size) {
    const float* x = (const float*)d_in[0];
    (void)in_sizes; (void)n_in; (void)out_size;
    cudaFuncSetAttribute(knn_kernel, cudaFuncAttributeMaxDynamicSharedMemorySize, SMEM_TOTAL);
    prep_kernel<<<N / 128, 128>>>(x);
    dim3 grid(N / ROWS, JSPLITS);
    knn_kernel<<<grid, THREADS, SMEM_TOTAL>>>();
    merge_kernel<<<N / 128, 128>>>();
    loss_kernel<<<1, 1024>>>((float*)d_out);
}